// round 13
// baseline (speedup 1.0000x reference)
#include <cuda_runtime.h>
#include <cuda_bf16.h>

// Fixed problem shapes
#define NN      100000      // total nodes
#define EE      1600000     // total edges
#define EPG     32000       // edges per graph
#define NZPG    48000       // framelet nnz per graph
#define BB      50          // graphs
#define NPG     2000        // nodes per graph
#define BANDS   3
#define HH      64
#define CC      10

#define GRID_BLOCKS 148
#define TILE_R  128
#define NT128   ((NN + TILE_R - 1) / TILE_R)   // 782
#define CHUNK   4
#define DSMEM   131072      // dynamic smem bytes (agg chunk needs 128000)

// -------- scratch (static device globals) --------
__device__ float g_bufA[NN * HH];
__device__ float g_bufB[NN * HH];
__device__ float g_dinv[NN];
__device__ int   g_rowptr[NN + 1];
__device__ int   g_cols[EE];
__device__ float g_wnode[NN * BANDS];
__device__ int   g_ctr1 = 0;            // gemm1 work-steal counter
__device__ int   g_ticket[GRID_BLOCKS]; // per-block ticket broadcast

// -------- grid barrier state --------
__device__ unsigned g_arrive = 0;
__device__ volatile unsigned g_gen = 0;

__device__ __forceinline__ void grid_sync() {
    __syncthreads();
    if (threadIdx.x == 0) {
        unsigned gen = g_gen;
        __threadfence();
        if (atomicAdd(&g_arrive, 1) == GRID_BLOCKS - 1) {
            atomicExch(&g_arrive, 0);
            __threadfence();
            g_gen = gen + 1;
        } else {
            while (g_gen == gen) { __nanosleep(32); }
        }
        __threadfence();
    }
    __syncthreads();
}

// ---------------- per-graph CSR build (one block) ----------------
__device__ void build_phase(char* dsm, int g, const int* __restrict__ row,
                            const int* __restrict__ col) {
    int* cnt  = (int*)dsm;              // [NPG]
    int* wsum = (int*)(dsm + NPG * 4);  // [32]
    int t = threadIdx.x;
    int nbase = g * NPG;
    int ebase = g * EPG;

    for (int i = t; i < NPG; i += 1024) cnt[i] = 0;
    __syncthreads();
    for (int e = ebase + t; e < ebase + EPG; e += 1024)
        atomicAdd(&cnt[row[e] - nbase], 1);
    __syncthreads();

    // pair-per-thread exclusive scan over 2000 counters
    int a = 0, b = 0;
    if (t < 1000) { a = cnt[2 * t]; b = cnt[2 * t + 1]; }
    int lane = t & 31, wid = t >> 5;
    int s = a + b;
    int inc = s;
#pragma unroll
    for (int o = 1; o < 32; o <<= 1) {
        int v = __shfl_up_sync(0xffffffffu, inc, o);
        if (lane >= o) inc += v;
    }
    if (lane == 31) wsum[wid] = inc;
    __syncthreads();
    if (wid == 0) {
        int w = wsum[lane];
#pragma unroll
        for (int o = 1; o < 32; o <<= 1) {
            int v = __shfl_up_sync(0xffffffffu, w, o);
            if (lane >= o) w += v;
        }
        wsum[lane] = w;
    }
    __syncthreads();
    int wbase = (wid > 0) ? wsum[wid - 1] : 0;
    int excl = wbase + inc - s;
    __syncthreads();
    if (t < 1000) {
        int o0 = excl, o1 = excl + a;
        cnt[2 * t]     = o0;
        cnt[2 * t + 1] = o1;
        g_rowptr[nbase + 2 * t]     = ebase + o0;
        g_rowptr[nbase + 2 * t + 1] = ebase + o1;
        g_dinv[nbase + 2 * t]     = rsqrtf((float)(a + 1));
        g_dinv[nbase + 2 * t + 1] = rsqrtf((float)(b + 1));
    }
    if (g == 0 && t == 0) g_rowptr[NN] = EE;
    __syncthreads();
    for (int e = ebase + t; e < ebase + EPG; e += 1024) {
        int r = row[e] - nbase;
        int p = atomicAdd(&cnt[r], 1);
        g_cols[ebase + p] = col[e];
    }
    __syncthreads();   // REQUIRED: smem is re-used (GEMM Ws) right after
}

// ---------------- per-graph framelet weight table ----------------
__device__ void frame_phase(char* dsm, int g, const int* __restrict__ fr,
                            const int* __restrict__ fc, const float* __restrict__ fv,
                            const int* __restrict__ dix) {
    float* fw = (float*)dsm;   // [NPG*BANDS]
    int t = threadIdx.x;
    for (int i = t; i < NPG * BANDS; i += 1024) fw[i] = 0.0f;
    __syncthreads();
    int base = g * NZPG;
    int nbase = g * NPG;
    for (int e = base + t; e < base + NZPG; e += 1024) {
        int r = fr[e];
        int c = fc[e] - nbase;
        float v = fv[e];
        int band = dix[r];
        atomicAdd(&fw[c * BANDS + band], v);
    }
    __syncthreads();
    int obase = g * NPG * BANDS;
    for (int i = t; i < NPG * BANDS; i += 1024) g_wnode[obase + i] = fw[i];
    __syncthreads();   // REQUIRED: smem re-used right after
}

// -------- one 128x64 GEMM tile --------
// scale_out: multiply rows by g_dinv in epilogue (for gemm2); raw for gemm1.
__device__ __forceinline__ void gemm_tile(float* Ws, float* As, const float* __restrict__ A,
                                          float* __restrict__ C, int tile, bool scale_out) {
    int t = threadIdx.x;
    int r0 = tile * TILE_R;
    __syncthreads();
#pragma unroll
    for (int i = 0; i < 8; i++) {
        int idx = t + i * 1024;
        int r = idx >> 6, k = idx & 63;
        int gr = r0 + r;
        As[r * 64 + k] = (gr < NN) ? A[gr * 64 + k] : 0.0f;
    }
    __syncthreads();
    int tx = t & 15, ty = t >> 4;   // ty: 0..63 -> rows ty, ty+64
    float a00 = 0.f, a01 = 0.f, a02 = 0.f, a03 = 0.f;
    float a10 = 0.f, a11 = 0.f, a12 = 0.f, a13 = 0.f;
#pragma unroll
    for (int k = 0; k < 64; k++) {
        float4 w4 = *(const float4*)&Ws[k * 64 + tx * 4];
        float av0 = As[ty * 64 + k];
        float av1 = As[(ty + 64) * 64 + k];
        a00 += av0 * w4.x; a01 += av0 * w4.y; a02 += av0 * w4.z; a03 += av0 * w4.w;
        a10 += av1 * w4.x; a11 += av1 * w4.y; a12 += av1 * w4.z; a13 += av1 * w4.w;
    }
    int gr0 = r0 + ty, gr1 = r0 + ty + 64;
    if (gr0 < NN) {
        float d = scale_out ? g_dinv[gr0] : 1.0f;
        *(float4*)&C[gr0 * 64 + tx * 4] = make_float4(d * a00, d * a01, d * a02, d * a03);
    }
    if (gr1 < NN) {
        float d = scale_out ? g_dinv[gr1] : 1.0f;
        *(float4*)&C[gr1 * 64 + tx * 4] = make_float4(d * a10, d * a11, d * a12, d * a13);
    }
}

__device__ void load_W(float* Ws, const float* __restrict__ W) {
    for (int idx = threadIdx.x; idx < 4096; idx += 1024) Ws[idx] = W[idx];
}

// ------- smem-staged GCN aggregation -------
// Unit = (graph, 16-feature chunk). Stage s(j)*h[j, chunk] into smem
// (s = dinv for layer 1 raw input, 1 for pre-scaled layer 2), then
// out[r] = relu( dinv[r] * (sm[r] + sum_c sm[c]) + b ).
__device__ void agg_smem(char* dsm, const float* __restrict__ hd,
                         const float* __restrict__ bias, float* __restrict__ out,
                         bool scale_fill) {
    float* smh = (float*)dsm;   // [NPG * 16]
    for (int u = blockIdx.x; u < BB * 4; u += GRID_BLOCKS) {
        int g = u >> 2, q = u & 3;
        int gbase = g * NPG;
        __syncthreads();   // previous unit's smem reads complete
        // fill: 2000 rows x 16 floats, float4 granularity
        for (int idx = threadIdx.x; idx < NPG * 4; idx += 1024) {
            int j = idx >> 2, f4 = idx & 3;
            float4 v = *(const float4*)&hd[(gbase + j) * 64 + q * 16 + f4 * 4];
            if (scale_fill) {
                float s = g_dinv[gbase + j];
                v.x *= s; v.y *= s; v.z *= s; v.w *= s;
            }
            ((float4*)smh)[idx] = v;
        }
        __syncthreads();
        int hw = threadIdx.x >> 4;      // 0..63 half-warps
        int l  = threadIdx.x & 15;
        float bq = bias[q * 16 + l];
        for (int r = hw; r < NPG; r += 64) {
            int gr = gbase + r;
            float dr = g_dinv[gr];
            float acc = smh[r * 16 + l];         // self loop
            int e0 = g_rowptr[gr], e1 = g_rowptr[gr + 1];
            int e = e0;
            for (; e + 4 <= e1; e += 4) {
                int c0 = g_cols[e + 0] - gbase;
                int c1 = g_cols[e + 1] - gbase;
                int c2 = g_cols[e + 2] - gbase;
                int c3 = g_cols[e + 3] - gbase;
                acc += smh[c0 * 16 + l] + smh[c1 * 16 + l]
                     + smh[c2 * 16 + l] + smh[c3 * 16 + l];
            }
            for (; e < e1; e++) acc += smh[(g_cols[e] - gbase) * 16 + l];
            out[gr * 64 + q * 16 + l] = fmaxf(dr * acc + bq, 0.0f);
        }
    }
}

// ------- fused pool + head for one graph (one block) -------
__device__ void poolhead_phase(char* dsm, int g, const float* __restrict__ h,
                               const float* __restrict__ fcW1, const float* __restrict__ fcb1,
                               const float* __restrict__ fcW2, const float* __restrict__ fcb2,
                               float* __restrict__ out) {
    float* part = (float*)dsm;            // [16][3][64]
    float* xp   = part + 16 * 3 * 64;     // [192]
    float* hid  = xp + 192;               // [64]
    int t = threadIdx.x;
    int f = t & 63, sub = t >> 6;   // 16 subs of 64 threads
    float a0 = 0.f, a1 = 0.f, a2 = 0.f;
    int base = g * NPG;
    for (int j = base + sub; j < base + NPG; j += 16) {
        float w0 = g_wnode[j * 3 + 0];
        float w1 = g_wnode[j * 3 + 1];
        float w2 = g_wnode[j * 3 + 2];
        float hv = h[j * 64 + f];
        a0 += w0 * hv; a1 += w1 * hv; a2 += w2 * hv;
    }
    __syncthreads();
    part[(sub * 3 + 0) * 64 + f] = a0;
    part[(sub * 3 + 1) * 64 + f] = a1;
    part[(sub * 3 + 2) * 64 + f] = a2;
    __syncthreads();
    if (t < 192) {
        float s = 0.f;
#pragma unroll
        for (int p = 0; p < 16; p++) s += part[(p * 3 + (t >> 6)) * 64 + (t & 63)];
        xp[t] = s;
    }
    __syncthreads();
    if (t < HH) {
        float acc = fcb1[t];
#pragma unroll 8
        for (int k = 0; k < BANDS * HH; k++) acc += xp[k] * fcW1[k * HH + t];
        hid[t] = fmaxf(acc, 0.0f);
    }
    __syncthreads();
    if (t < CC) {
        float o = fcb2[t];
#pragma unroll
        for (int k = 0; k < HH; k++) o += hid[k] * fcW2[k * CC + t];
        out[g * CC + t] = o;
    }
}

// ---------------- the mega-kernel ----------------
__global__ void __launch_bounds__(1024, 1)
k_mega(const float* __restrict__ x, const int* __restrict__ row, const int* __restrict__ col,
       const int* __restrict__ fr, const int* __restrict__ fc, const float* __restrict__ fv,
       const int* __restrict__ dix,
       const float* __restrict__ W1, const float* __restrict__ b1,
       const float* __restrict__ W2, const float* __restrict__ b2,
       const float* __restrict__ fcW1, const float* __restrict__ fcb1,
       const float* __restrict__ fcW2, const float* __restrict__ fcb2,
       float* __restrict__ out) {
    extern __shared__ char dsm[];
    float* Ws = (float*)dsm;                 // [64*64]
    float* As = (float*)(dsm + 16384);       // [128*64]
    int bid = blockIdx.x;

    // P0: build (0-49) | frame (50-99), then ALL blocks work-steal GEMM1
    // tiles (raw product; layer-1 scaling applied during agg1 fill).
    if (bid < BB) {
        build_phase(dsm, bid, row, col);
    } else if (bid < 2 * BB) {
        frame_phase(dsm, bid - BB, fr, fc, fv, dix);
    }
    {
        load_W(Ws, W1);
        for (;;) {
            __syncthreads();
            if (threadIdx.x == 0)
                g_ticket[blockIdx.x] = atomicAdd(&g_ctr1, CHUNK);
            __syncthreads();
            int t0 = g_ticket[blockIdx.x];
            if (t0 >= NT128) break;
            int t1 = min(t0 + CHUNK, NT128);
            for (int tile = t0; tile < t1; tile++)
                gemm_tile(Ws, As, x, g_bufA, tile, false);
        }
    }
    grid_sync();
    if (bid == GRID_BLOCKS - 1 && threadIdx.x == 0) g_ctr1 = 0;  // reset for graph replay

    // P1: aggregation layer 1 (smem-staged, dinv applied at fill)
    agg_smem(dsm, g_bufA, b1, g_bufB, true);
    grid_sync();

    // P2: GEMM2 (static partition), epilogue pre-scales by dinv
    load_W(Ws, W2);
    for (int tile = bid; tile < NT128; tile += GRID_BLOCKS)
        gemm_tile(Ws, As, g_bufB, g_bufA, tile, true);
    grid_sync();

    // P3: aggregation layer 2 (input pre-scaled; fill unscaled)
    agg_smem(dsm, g_bufA, b2, g_bufB, false);
    grid_sync();

    // P4: fused pool + MLP head
    if (bid < BB)
        poolhead_phase(dsm, bid, g_bufB, fcW1, fcb1, fcW2, fcb2, out);
}

extern "C" void kernel_launch(void* const* d_in, const int* in_sizes, int n_in,
                              void* d_out, int out_size) {
    (void)in_sizes; (void)n_in; (void)out_size;
    const float* x    = (const float*)d_in[0];
    const int*   ei   = (const int*)d_in[1];
    const int*   frow = (const int*)d_in[3];
    const int*   fcol = (const int*)d_in[4];
    const float* fval = (const float*)d_in[5];
    const int*   dix  = (const int*)d_in[6];
    const float* W1   = (const float*)d_in[8];
    const float* b1   = (const float*)d_in[9];
    const float* W2   = (const float*)d_in[10];
    const float* b2   = (const float*)d_in[11];
    const float* fcW1 = (const float*)d_in[12];
    const float* fcb1 = (const float*)d_in[13];
    const float* fcW2 = (const float*)d_in[14];
    const float* fcb2 = (const float*)d_in[15];
    float* out = (float*)d_out;

    const int* row = ei;        // edge_index[0]
    const int* col = ei + EE;   // edge_index[1]

    // Opt-in to >48KB dynamic smem (idempotent; not a stream op, capture-safe)
    cudaFuncSetAttribute(k_mega, cudaFuncAttributeMaxDynamicSharedMemorySize, DSMEM);

    k_mega<<<GRID_BLOCKS, 1024, DSMEM>>>(x, row, col, frow, fcol, fval, dix,
                                         W1, b1, W2, b2, fcW1, fcb1, fcW2, fcb2, out);
}

// round 16
// speedup vs baseline: 1.4851x; 1.4851x over previous
#include <cuda_runtime.h>
#include <cuda_bf16.h>

// Fixed problem shapes
#define NN      100000      // total nodes
#define EE      1600000     // total edges
#define EPG     32000       // edges per graph
#define NZPG    48000       // framelet nnz per graph
#define BB      50          // graphs
#define NPG     2000        // nodes per graph
#define BANDS   3
#define HH      64
#define CC      10

#define GRID_BLOCKS 148
#define TILE_R  128
#define NT128   ((NN + TILE_R - 1) / TILE_R)   // 782
#define CHUNK   4

// -------- scratch (static device globals) --------
__device__ float g_bufA[NN * HH];
__device__ float g_bufB[NN * HH];
__device__ float g_dinv[NN];
__device__ int   g_rowptr[NN + 1];
__device__ int   g_cols[EE];
__device__ float g_wnode[NN * BANDS];
__device__ int   g_ctr1 = 0;            // gemm1 work-steal counter
__device__ int   g_ticket[GRID_BLOCKS]; // per-block ticket broadcast

// -------- grid barrier state --------
__device__ unsigned g_arrive = 0;
__device__ volatile unsigned g_gen = 0;

__device__ __forceinline__ void grid_sync() {
    __syncthreads();
    if (threadIdx.x == 0) {
        unsigned gen = g_gen;
        __threadfence();
        if (atomicAdd(&g_arrive, 1) == GRID_BLOCKS - 1) {
            atomicExch(&g_arrive, 0);
            __threadfence();
            g_gen = gen + 1;
        } else {
            while (g_gen == gen) { __nanosleep(32); }
        }
        __threadfence();
    }
    __syncthreads();
}

// -------- shared memory union across phases (48KB static) --------
union SmemU {
    struct { int cnt[NPG]; int wsum[32]; } build;              // ~8.1 KB
    float fw[NPG * BANDS];                                     // 24 KB
    struct { float Ws[64][64]; float As[TILE_R][64]; } gm;     // 48 KB
    struct { float part[16][3][64]; float xp[192]; float hid[64]; } ph; // 13.3 KB
};

// ---------------- per-graph CSR build (one block) ----------------
__device__ void build_phase(SmemU& sm, int g, const int* __restrict__ row,
                            const int* __restrict__ col) {
    int t = threadIdx.x;
    int nbase = g * NPG;
    int ebase = g * EPG;

    for (int i = t; i < NPG; i += 1024) sm.build.cnt[i] = 0;
    __syncthreads();
    for (int e = ebase + t; e < ebase + EPG; e += 1024)
        atomicAdd(&sm.build.cnt[row[e] - nbase], 1);
    __syncthreads();

    // pair-per-thread exclusive scan over 2000 counters
    int a = 0, b = 0;
    if (t < 1000) { a = sm.build.cnt[2 * t]; b = sm.build.cnt[2 * t + 1]; }
    int lane = t & 31, wid = t >> 5;
    int s = a + b;
    int inc = s;
#pragma unroll
    for (int o = 1; o < 32; o <<= 1) {
        int v = __shfl_up_sync(0xffffffffu, inc, o);
        if (lane >= o) inc += v;
    }
    if (lane == 31) sm.build.wsum[wid] = inc;
    __syncthreads();
    if (wid == 0) {
        int w = sm.build.wsum[lane];
#pragma unroll
        for (int o = 1; o < 32; o <<= 1) {
            int v = __shfl_up_sync(0xffffffffu, w, o);
            if (lane >= o) w += v;
        }
        sm.build.wsum[lane] = w;
    }
    __syncthreads();
    int wbase = (wid > 0) ? sm.build.wsum[wid - 1] : 0;
    int excl = wbase + inc - s;
    __syncthreads();
    if (t < 1000) {
        int o0 = excl, o1 = excl + a;
        sm.build.cnt[2 * t]     = o0;
        sm.build.cnt[2 * t + 1] = o1;
        g_rowptr[nbase + 2 * t]     = ebase + o0;
        g_rowptr[nbase + 2 * t + 1] = ebase + o1;
        g_dinv[nbase + 2 * t]     = rsqrtf((float)(a + 1));
        g_dinv[nbase + 2 * t + 1] = rsqrtf((float)(b + 1));
    }
    if (g == 0 && t == 0) g_rowptr[NN] = EE;
    __syncthreads();
    for (int e = ebase + t; e < ebase + EPG; e += 1024) {
        int r = row[e] - nbase;
        int p = atomicAdd(&sm.build.cnt[r], 1);
        g_cols[ebase + p] = col[e];
    }
    __syncthreads();   // REQUIRED: smem union re-used (GEMM Ws) right after
}

// ---------------- per-graph framelet weight table ----------------
__device__ void frame_phase(SmemU& sm, int g, const int* __restrict__ fr,
                            const int* __restrict__ fc, const float* __restrict__ fv,
                            const int* __restrict__ dix) {
    int t = threadIdx.x;
    for (int i = t; i < NPG * BANDS; i += 1024) sm.fw[i] = 0.0f;
    __syncthreads();
    int base = g * NZPG;
    int nbase = g * NPG;
    for (int e = base + t; e < base + NZPG; e += 1024) {
        int r = fr[e];
        int c = fc[e] - nbase;
        float v = fv[e];
        int band = dix[r];
        atomicAdd(&sm.fw[c * BANDS + band], v);
    }
    __syncthreads();
    int obase = g * NPG * BANDS;
    for (int i = t; i < NPG * BANDS; i += 1024) g_wnode[obase + i] = sm.fw[i];
    __syncthreads();   // REQUIRED: smem union re-used right after
}

// -------- one 128x64 GEMM tile --------
__device__ __forceinline__ void gemm_tile(SmemU& sm, const float* __restrict__ A,
                                          float* __restrict__ C, int tile, bool scale_out) {
    int t = threadIdx.x;
    int r0 = tile * TILE_R;
    __syncthreads();
#pragma unroll
    for (int i = 0; i < 8; i++) {
        int idx = t + i * 1024;
        int r = idx >> 6, k = idx & 63;
        int gr = r0 + r;
        sm.gm.As[r][k] = (gr < NN) ? A[gr * 64 + k] : 0.0f;
    }
    __syncthreads();
    int tx = t & 15, ty = t >> 4;   // ty: 0..63 -> rows ty, ty+64
    float a00 = 0.f, a01 = 0.f, a02 = 0.f, a03 = 0.f;
    float a10 = 0.f, a11 = 0.f, a12 = 0.f, a13 = 0.f;
#pragma unroll
    for (int k = 0; k < 64; k++) {
        float4 w4 = *(const float4*)&sm.gm.Ws[k][tx * 4];
        float av0 = sm.gm.As[ty][k];
        float av1 = sm.gm.As[ty + 64][k];
        a00 += av0 * w4.x; a01 += av0 * w4.y; a02 += av0 * w4.z; a03 += av0 * w4.w;
        a10 += av1 * w4.x; a11 += av1 * w4.y; a12 += av1 * w4.z; a13 += av1 * w4.w;
    }
    int gr0 = r0 + ty, gr1 = r0 + ty + 64;
    if (gr0 < NN) {
        float d = scale_out ? g_dinv[gr0] : 1.0f;
        *(float4*)&C[gr0 * 64 + tx * 4] = make_float4(d * a00, d * a01, d * a02, d * a03);
    }
    if (gr1 < NN) {
        float d = scale_out ? g_dinv[gr1] : 1.0f;
        *(float4*)&C[gr1 * 64 + tx * 4] = make_float4(d * a10, d * a11, d * a12, d * a13);
    }
}

__device__ void load_W(SmemU& sm, const float* __restrict__ W) {
    for (int idx = threadIdx.x; idx < 4096; idx += 1024)
        sm.gm.Ws[idx >> 6][idx & 63] = W[idx];
}

// ------- GCN aggregation: warp per row, float4 lanes, 2 edges/iteration -------
// lanes 0-15 process even-offset edges, lanes 16-31 odd-offset edges of the
// SAME row; each lane covers features fidx*4..fidx*4+3 via LDG.128.
// scale_read: input raw -> multiply gathered rows (and self) by dinv.
__device__ void agg_f4(const float* __restrict__ hd, const float* __restrict__ bias,
                       float* __restrict__ out, bool scale_read) {
    int bid = blockIdx.x;
    int r_begin = (int)((long long)bid * NN / GRID_BLOCKS);
    int r_end   = (int)((long long)(bid + 1) * NN / GRID_BLOCKS);
    int w = threadIdx.x >> 5, lane = threadIdx.x & 31;
    int fidx = lane & 15, half = lane >> 4;
    const float4* h4 = (const float4*)hd;
    float4 bq = ((const float4*)bias)[fidx];

    for (int r = r_begin + w; r < r_end; r += 32) {
        float dr = g_dinv[r];
        float4 acc = make_float4(0.f, 0.f, 0.f, 0.f);
        if (half == 0) {
            float4 sv = h4[r * 16 + fidx];
            float s = scale_read ? dr : 1.0f;
            acc.x = s * sv.x; acc.y = s * sv.y; acc.z = s * sv.z; acc.w = s * sv.w;
        }
        int e0 = g_rowptr[r], e1 = g_rowptr[r + 1];
        int e = e0 + half;
        if (scale_read) {
            for (; e + 6 < e1; e += 8) {
                int c0 = g_cols[e], c1 = g_cols[e + 2], c2 = g_cols[e + 4], c3 = g_cols[e + 6];
                float d0 = g_dinv[c0], d1 = g_dinv[c1], d2 = g_dinv[c2], d3 = g_dinv[c3];
                float4 v0 = h4[c0 * 16 + fidx];
                float4 v1 = h4[c1 * 16 + fidx];
                float4 v2 = h4[c2 * 16 + fidx];
                float4 v3 = h4[c3 * 16 + fidx];
                acc.x += d0 * v0.x + d1 * v1.x + d2 * v2.x + d3 * v3.x;
                acc.y += d0 * v0.y + d1 * v1.y + d2 * v2.y + d3 * v3.y;
                acc.z += d0 * v0.z + d1 * v1.z + d2 * v2.z + d3 * v3.z;
                acc.w += d0 * v0.w + d1 * v1.w + d2 * v2.w + d3 * v3.w;
            }
            for (; e < e1; e += 2) {
                int c = g_cols[e];
                float dc = g_dinv[c];
                float4 v = h4[c * 16 + fidx];
                acc.x += dc * v.x; acc.y += dc * v.y; acc.z += dc * v.z; acc.w += dc * v.w;
            }
        } else {
            for (; e + 6 < e1; e += 8) {
                int c0 = g_cols[e], c1 = g_cols[e + 2], c2 = g_cols[e + 4], c3 = g_cols[e + 6];
                float4 v0 = h4[c0 * 16 + fidx];
                float4 v1 = h4[c1 * 16 + fidx];
                float4 v2 = h4[c2 * 16 + fidx];
                float4 v3 = h4[c3 * 16 + fidx];
                acc.x += v0.x + v1.x + v2.x + v3.x;
                acc.y += v0.y + v1.y + v2.y + v3.y;
                acc.z += v0.z + v1.z + v2.z + v3.z;
                acc.w += v0.w + v1.w + v2.w + v3.w;
            }
            for (; e < e1; e += 2) {
                int c = g_cols[e];
                float4 v = h4[c * 16 + fidx];
                acc.x += v.x; acc.y += v.y; acc.z += v.z; acc.w += v.w;
            }
        }
        // combine the two halves
        acc.x += __shfl_xor_sync(0xffffffffu, acc.x, 16);
        acc.y += __shfl_xor_sync(0xffffffffu, acc.y, 16);
        acc.z += __shfl_xor_sync(0xffffffffu, acc.z, 16);
        acc.w += __shfl_xor_sync(0xffffffffu, acc.w, 16);
        if (half == 0) {
            float4 o;
            o.x = fmaxf(dr * acc.x + bq.x, 0.0f);
            o.y = fmaxf(dr * acc.y + bq.y, 0.0f);
            o.z = fmaxf(dr * acc.z + bq.z, 0.0f);
            o.w = fmaxf(dr * acc.w + bq.w, 0.0f);
            ((float4*)out)[r * 16 + fidx] = o;
        }
    }
}

// ------- fused pool + head for one graph (one block) -------
__device__ void poolhead_phase(SmemU& sm, int g, const float* __restrict__ h,
                               const float* __restrict__ fcW1, const float* __restrict__ fcb1,
                               const float* __restrict__ fcW2, const float* __restrict__ fcb2,
                               float* __restrict__ out) {
    int t = threadIdx.x;
    int f = t & 63, sub = t >> 6;   // 16 subs of 64 threads
    float a0 = 0.f, a1 = 0.f, a2 = 0.f;
    int base = g * NPG;
    for (int j = base + sub; j < base + NPG; j += 16) {
        float w0 = g_wnode[j * 3 + 0];
        float w1 = g_wnode[j * 3 + 1];
        float w2 = g_wnode[j * 3 + 2];
        float hv = h[j * 64 + f];
        a0 += w0 * hv; a1 += w1 * hv; a2 += w2 * hv;
    }
    __syncthreads();   // prior phase smem use done before overwrite
    sm.ph.part[sub][0][f] = a0;
    sm.ph.part[sub][1][f] = a1;
    sm.ph.part[sub][2][f] = a2;
    __syncthreads();
    if (t < 192) {
        float s = 0.f;
#pragma unroll
        for (int p = 0; p < 16; p++) s += sm.ph.part[p][t >> 6][t & 63];
        sm.ph.xp[t] = s;
    }
    __syncthreads();
    if (t < HH) {
        float acc = fcb1[t];
#pragma unroll 8
        for (int k = 0; k < BANDS * HH; k++) acc += sm.ph.xp[k] * fcW1[k * HH + t];
        sm.ph.hid[t] = fmaxf(acc, 0.0f);
    }
    __syncthreads();
    if (t < CC) {
        float o = fcb2[t];
#pragma unroll
        for (int k = 0; k < HH; k++) o += sm.ph.hid[k] * fcW2[k * CC + t];
        out[g * CC + t] = o;
    }
}

// ---------------- the mega-kernel ----------------
__global__ void __launch_bounds__(1024, 1)
k_mega(const float* __restrict__ x, const int* __restrict__ row, const int* __restrict__ col,
       const int* __restrict__ fr, const int* __restrict__ fc, const float* __restrict__ fv,
       const int* __restrict__ dix,
       const float* __restrict__ W1, const float* __restrict__ b1,
       const float* __restrict__ W2, const float* __restrict__ b2,
       const float* __restrict__ fcW1, const float* __restrict__ fcb1,
       const float* __restrict__ fcW2, const float* __restrict__ fcb2,
       float* __restrict__ out) {
    __shared__ SmemU sm;
    int bid = blockIdx.x;

    // P0: build (0-49) | frame (50-99), then ALL blocks work-steal GEMM1
    // tiles (raw product; layer-1 scaling applied on read in agg1).
    if (bid < BB) {
        build_phase(sm, bid, row, col);
    } else if (bid < 2 * BB) {
        frame_phase(sm, bid - BB, fr, fc, fv, dix);
    }
    {
        load_W(sm, W1);
        for (;;) {
            __syncthreads();
            if (threadIdx.x == 0)
                g_ticket[blockIdx.x] = atomicAdd(&g_ctr1, CHUNK);
            __syncthreads();
            int t0 = g_ticket[blockIdx.x];
            if (t0 >= NT128) break;
            int t1 = min(t0 + CHUNK, NT128);
            for (int tile = t0; tile < t1; tile++)
                gemm_tile(sm, x, g_bufA, tile, false);
        }
    }
    grid_sync();
    if (bid == GRID_BLOCKS - 1 && threadIdx.x == 0) g_ctr1 = 0;  // reset for graph replay

    // P1: aggregation layer 1 (raw input, scale on read)
    agg_f4(g_bufA, b1, g_bufB, true);
    grid_sync();

    // P2: GEMM2 (static partition), epilogue pre-scales by dinv
    load_W(sm, W2);
    for (int tile = bid; tile < NT128; tile += GRID_BLOCKS)
        gemm_tile(sm, g_bufB, g_bufA, tile, true);
    grid_sync();

    // P3: aggregation layer 2 (pre-scaled input)
    agg_f4(g_bufA, b2, g_bufB, false);
    grid_sync();

    // P4: fused pool + MLP head
    if (bid < BB)
        poolhead_phase(sm, bid, g_bufB, fcW1, fcb1, fcW2, fcb2, out);
}

extern "C" void kernel_launch(void* const* d_in, const int* in_sizes, int n_in,
                              void* d_out, int out_size) {
    (void)in_sizes; (void)n_in; (void)out_size;
    const float* x    = (const float*)d_in[0];
    const int*   ei   = (const int*)d_in[1];
    const int*   frow = (const int*)d_in[3];
    const int*   fcol = (const int*)d_in[4];
    const float* fval = (const float*)d_in[5];
    const int*   dix  = (const int*)d_in[6];
    const float* W1   = (const float*)d_in[8];
    const float* b1   = (const float*)d_in[9];
    const float* W2   = (const float*)d_in[10];
    const float* b2   = (const float*)d_in[11];
    const float* fcW1 = (const float*)d_in[12];
    const float* fcb1 = (const float*)d_in[13];
    const float* fcW2 = (const float*)d_in[14];
    const float* fcb2 = (const float*)d_in[15];
    float* out = (float*)d_out;

    const int* row = ei;        // edge_index[0]
    const int* col = ei + EE;   // edge_index[1]

    k_mega<<<GRID_BLOCKS, 1024>>>(x, row, col, frow, fcol, fval, dix,
                                  W1, b1, W2, b2, fcW1, fcb1, fcW2, fcb2, out);
}